// round 5
// baseline (speedup 1.0000x reference)
#include <cuda_runtime.h>

#define NB 16
#define NH 16
#define NI 512
#define NE 512
#define IE (NI * NE)
#define JSPLIT 4

// Scratch (device globals; allocations are forbidden)
__device__ float g_embp[JSPLIT][NB * NH * NE];  // 2 MB: emb partials (j-split = 4)

// ---------------------------------------------------------------------------
// Kernel 1: emb[b,h,e] = sum_j x[b,j,e] * W_v[h,j,e]   (j-split partials)
// Thread tile 4b x 4h x 4e (float4 accumulators): per j, 8 LDG.128 + 64 FMA
// (vs 16 LDG.32 before -- emb was LDG-issue-bound). Block = 8b x 8h x 32e x
// 128j; 256 threads = 8 j-slices x 32 positions (eq[3]|bq[1]|hq[1]).
// Grid 256 = 16 ec x 2 hg x 2 bg x 4 js -> one full wave at 2 blocks/SM.
// Also pre-initializes out with the broadcast bias (2 floats/thread).
// ---------------------------------------------------------------------------
__global__ __launch_bounds__(256, 2) void emb_kernel(const float* __restrict__ x,
                                                     const float* __restrict__ wv,
                                                     const float* __restrict__ bias,
                                                     float* __restrict__ out) {
    const int t   = threadIdx.x;
    const int bid = blockIdx.x;        // 256 blocks

    // Bias init of the output (gemm_kernel atomically accumulates on top).
    {
        const int oidx = bid * 256 + t;            // 0 .. 65535
        out[oidx]         = bias[oidx & (NE - 1)];
        out[oidx + 65536] = bias[oidx & (NE - 1)];
    }

    const int sl  = t >> 5;            // j slice (warp id) 0..7
    const int pos = t & 31;            // position within slice
    const int eq  = pos >> 2;          // e quad 0..7
    const int bq  = (pos >> 1) & 1;    // b half of 8
    const int hq  = pos & 1;           // h half of 8

    const int ec  = bid & 15;          // e chunk 0..15
    const int hg  = (bid >> 4) & 1;    // h half
    const int bg  = (bid >> 5) & 1;    // b half
    const int js  = bid >> 6;          // j split 0..3

    const int e0 = ec * 32 + eq * 4;   // 16B-aligned
    const float* xp = x  + (bg * 8 + bq * 4) * IE + e0;
    const float* wp = wv + (hg * 8 + hq * 4) * IE + e0;

    float4 acc[4][4];
#pragma unroll
    for (int i = 0; i < 4; ++i)
#pragma unroll
        for (int k = 0; k < 4; ++k) acc[i][k] = make_float4(0.f, 0.f, 0.f, 0.f);

    const int j0 = js * 128;
#pragma unroll 2
    for (int jj = 0; jj < 16; ++jj) {
        const int joff = (j0 + sl + jj * 8) * NE;
        float4 xv[4], wv4[4];
#pragma unroll
        for (int i = 0; i < 4; ++i) xv[i]  = *(const float4*)(xp + i * IE + joff);
#pragma unroll
        for (int k = 0; k < 4; ++k) wv4[k] = *(const float4*)(wp + k * IE + joff);
#pragma unroll
        for (int i = 0; i < 4; ++i)
#pragma unroll
            for (int k = 0; k < 4; ++k) {
                acc[i][k].x = fmaf(xv[i].x, wv4[k].x, acc[i][k].x);
                acc[i][k].y = fmaf(xv[i].y, wv4[k].y, acc[i][k].y);
                acc[i][k].z = fmaf(xv[i].z, wv4[k].z, acc[i][k].z);
                acc[i][k].w = fmaf(xv[i].w, wv4[k].w, acc[i][k].w);
            }
    }

    // Reduce 8 j-slices. red4[slice][c][pos]: float4 lanes on pos -> both the
    // write (lanes vary pos) and the read (lanes vary pos) are conflict-free.
    __shared__ float4 red4[8][8][32];  // 32 KB per half
    const int posr = t & 31;
#pragma unroll
    for (int half = 0; half < 2; ++half) {
        __syncthreads();
#pragma unroll
        for (int c = 0; c < 8; ++c) {
            const int cf = half * 8 + c;           // bi*4 + hi
            red4[sl][c][pos] = acc[cf >> 2][cf & 3];
        }
        __syncthreads();
        {
            const int c = t >> 5;                  // 0..7
            float4 s = red4[0][c][posr];
#pragma unroll
            for (int q = 1; q < 8; ++q) {
                const float4 v = red4[q][c][posr];
                s.x += v.x; s.y += v.y; s.z += v.z; s.w += v.w;
            }
            const int cf  = half * 8 + c;
            const int bi  = cf >> 2, hi = cf & 3;
            const int eqr = posr >> 2, bqr = (posr >> 1) & 1, hqr = posr & 1;
            const int b = bg * 8 + bqr * 4 + bi;
            const int h = hg * 8 + hqr * 4 + hi;
            const int e = ec * 32 + eqr * 4;
            *(float4*)&g_embp[js][(b * NH + h) * NE + e] = s;
        }
    }
}

// ---------------------------------------------------------------------------
// Kernel 2: out[m][n] += sum_k emb[m][k]*w[n][k]  (bias already in out)
// M=256, N=512, K=512. Tiles 64x64, split-K=4 (K=128 per block, two 64-wide
// smem stages) -> 128 blocks. A-tile load folds the 4 j-split emb partials.
// Epilogue: REDG atomicAdd into the bias-initialized output.
// ---------------------------------------------------------------------------
__global__ __launch_bounds__(256) void gemm_kernel(const float* __restrict__ w,
                                                   float* __restrict__ out) {
    const int t   = threadIdx.x;
    const int bid = blockIdx.x;        // 128 = 4 mt x 8 nt x 4 kt
    const int kt  = bid & 3;
    const int nt  = (bid >> 2) & 7;
    const int mt  = bid >> 5;
    const int m0 = mt * 64, n0 = nt * 64;

    __shared__ __align__(16) float sa[64][68];  // [k][m]
    __shared__ __align__(16) float sb[64][68];  // [k][n]

    const int tx = t & 15;   // n micro-tile
    const int ty = t >> 4;   // m micro-tile
    float acc[4][4];
#pragma unroll
    for (int i = 0; i < 4; ++i)
#pragma unroll
        for (int j = 0; j < 4; ++j) acc[i][j] = 0.f;

#pragma unroll
    for (int kc = 0; kc < 2; ++kc) {
        const int k0 = kt * 128 + kc * 64;
        if (kc) __syncthreads();   // previous chunk's compute done before reload

#pragma unroll
        for (int r = 0; r < 4; ++r) {
            const int lin = t + r * 256;        // 0..1023 float4 slots
            const int row = lin >> 4;           // 0..63
            const int kq  = (lin & 15) * 4;     // 0..60
            const int aoff = (m0 + row) * NE + k0 + kq;
            float4 a = *(const float4*)&g_embp[0][aoff];
#pragma unroll
            for (int p = 1; p < JSPLIT; ++p) {
                const float4 v = *(const float4*)&g_embp[p][aoff];
                a.x += v.x; a.y += v.y; a.z += v.z; a.w += v.w;
            }
            sa[kq + 0][row] = a.x;
            sa[kq + 1][row] = a.y;
            sa[kq + 2][row] = a.z;
            sa[kq + 3][row] = a.w;
            const float4 b4 = *(const float4*)&w[(n0 + row) * NE + k0 + kq];
            sb[kq + 0][row] = b4.x;
            sb[kq + 1][row] = b4.y;
            sb[kq + 2][row] = b4.z;
            sb[kq + 3][row] = b4.w;
        }
        __syncthreads();

#pragma unroll 8
        for (int kk = 0; kk < 64; ++kk) {
            const float4 av = *(const float4*)&sa[kk][ty * 4];
            const float4 bv = *(const float4*)&sb[kk][tx * 4];
            const float a[4] = {av.x, av.y, av.z, av.w};
            const float b[4] = {bv.x, bv.y, bv.z, bv.w};
#pragma unroll
            for (int i = 0; i < 4; ++i)
#pragma unroll
                for (int j = 0; j < 4; ++j)
                    acc[i][j] = fmaf(a[i], b[j], acc[i][j]);
        }
    }

    // Split-K accumulate directly into the bias-initialized output.
#pragma unroll
    for (int i = 0; i < 4; ++i) {
        float* op = &out[(m0 + ty * 4 + i) * NE + n0 + tx * 4];
#pragma unroll
        for (int j = 0; j < 4; ++j)
            atomicAdd(op + j, acc[i][j]);
    }
}

extern "C" void kernel_launch(void* const* d_in, const int* in_sizes, int n_in,
                              void* d_out, int out_size) {
    const float* x    = (const float*)d_in[0];  // [16,1,512,512]
    // d_in[1] = W_q, d_in[2] = W_k: mathematically dead (softmax cols sum to 1)
    const float* wv   = (const float*)d_in[3];  // [1,16,512,512]
    const float* mlpw = (const float*)d_in[4];  // [512,512]
    const float* mlpb = (const float*)d_in[5];  // [512]
    float* out = (float*)d_out;                 // [16,16,512]

    emb_kernel<<<256, 256>>>(x, wv, mlpb, out);
    gemm_kernel<<<128, 256>>>(mlpw, out);
}

// round 6
// speedup vs baseline: 1.0932x; 1.0932x over previous
#include <cuda_runtime.h>

#define NB 16
#define NH 16
#define NI 512
#define NE 512
#define IE (NI * NE)
#define JSPLIT 4
#define GRID 256

// Scratch (device globals; allocations are forbidden)
__device__ float g_embp[JSPLIT][NB * NH * NE];  // 2 MB: emb partials
__device__ unsigned g_arrive = 0;               // barrier arrive counter (self-resets)
__device__ volatile unsigned g_release = 0;     // barrier generation (monotonic across replays)

// ---------------------------------------------------------------------------
// Single fused kernel, 256 blocks x 256 threads, all co-resident (2/SM x 148).
//  Phase 0: out = broadcast bias (gemm phase accumulates on top).
//  Phase 1: emb partials, g_embp[js][b,h,e] = sum_{j in slice} x[b,j,e]*Wv[h,j,e]
//           (R4's scalar-load form: 16 LDG.32 + 64 FMA per j, 8x8 reg tile).
//  Grid-wide software barrier (sense-reversal, replay-safe).
//  Phase 2: out += emb @ w^T. 256 tiles = 8mt(32m) x 8nt(64n) x 4kt(128k),
//           A-load folds the 4 j-split partials, REDG atomicAdd epilogue.
// ---------------------------------------------------------------------------
__global__ __launch_bounds__(256, 2) void fused_kernel(const float* __restrict__ x,
                                                       const float* __restrict__ wv,
                                                       const float* __restrict__ w,
                                                       const float* __restrict__ bias,
                                                       float* __restrict__ out) {
    const int t   = threadIdx.x;
    const int bid = blockIdx.x;        // 256 blocks

    __shared__ union {
        float red[8][32][32];                       // 32 KB (emb reduction)
        struct { float a[64][36]; float b[64][68]; } g;  // 26.6 KB (gemm tiles)
    } sm;

    // ---- Phase 0: bias init of the output --------------------------------
    {
        const int oidx = bid * 256 + t;            // 0 .. 65535
        const float bv = bias[oidx & (NE - 1)];    // (oidx+65536) % 512 == oidx % 512
        out[oidx]         = bv;
        out[oidx + 65536] = bv;
    }

    // ---- Phase 1: emb partials -------------------------------------------
    {
        const int el  = t & 31;            // e lane (coalesced)
        const int sl  = t >> 5;            // j slice (warp id) 0..7
        const int ec  = bid & 15;          // e chunk 0..15
        const int hg  = (bid >> 4) & 1;    // h half
        const int bg  = (bid >> 5) & 1;    // b half
        const int js  = bid >> 6;          // j split 0..3

        const int e = ec * 32 + el;
        const float* xp = x  + bg * 8 * IE + e;
        const float* wp = wv + hg * 8 * IE + e;

        float acc[8][8];
#pragma unroll
        for (int i = 0; i < 8; ++i)
#pragma unroll
            for (int k = 0; k < 8; ++k) acc[i][k] = 0.f;

        const int j0 = js * 128;
#pragma unroll 2
        for (int jj = 0; jj < 16; ++jj) {
            const int joff = (j0 + sl + jj * 8) * NE;
            float xv[8], wv8[8];
#pragma unroll
            for (int i = 0; i < 8; ++i) xv[i]  = __ldg(xp + i * IE + joff);
#pragma unroll
            for (int k = 0; k < 8; ++k) wv8[k] = __ldg(wp + k * IE + joff);
#pragma unroll
            for (int i = 0; i < 8; ++i)
#pragma unroll
                for (int k = 0; k < 8; ++k)
                    acc[i][k] = fmaf(xv[i], wv8[k], acc[i][k]);
        }

        const int b0 = bg * 8, h0 = hg * 8;
#pragma unroll
        for (int half = 0; half < 2; ++half) {
            __syncthreads();
#pragma unroll
            for (int ik = 0; ik < 32; ++ik) {
                const int ikf = half * 32 + ik;
                sm.red[sl][ik][el] = acc[ikf >> 3][ikf & 7];
            }
            __syncthreads();
#pragma unroll
            for (int r = 0; r < 4; ++r) {
                const int ik = r * 8 + sl;
                float s = 0.f;
#pragma unroll
                for (int q = 0; q < 8; ++q) s += sm.red[q][ik][el];
                const int ikf = half * 32 + ik;
                const int b = b0 + (ikf >> 3);
                const int h = h0 + (ikf & 7);
                g_embp[js][(b * NH + h) * NE + e] = s;
            }
        }
    }

    // ---- Grid-wide barrier (all 256 blocks resident: 2/SM x 148 = 296) ----
    __threadfence();     // publish this thread's g_embp / out writes
    __syncthreads();     // whole block done before representative arrives
    if (t == 0) {
        const unsigned gen = g_release;
        const unsigned ticket = atomicAdd(&g_arrive, 1u);
        if (ticket == GRID - 1) {
            g_arrive = 0;                    // reset for next replay
            __threadfence();
            atomicAdd((unsigned*)&g_release, 1u);
        } else {
            while (g_release == gen) { }
        }
    }
    __syncthreads();
    __threadfence();     // acquire: order g_embp reads after the flag

    // ---- Phase 2: out += emb @ w^T ----------------------------------------
    {
        const int kt = bid & 3;            // split-K 0..3 (K=128 each)
        const int nt = (bid >> 2) & 7;     // n tile 0..7 (64 wide)
        const int mt = bid >> 5;           // m tile 0..7 (32 wide)
        const int m0 = mt * 32, n0 = nt * 64;

        const int tx = t & 15;   // n micro-tile (4 wide)
        const int ty = t >> 4;   // m micro-tile (2 wide)
        float acc[2][4];
#pragma unroll
        for (int i = 0; i < 2; ++i)
#pragma unroll
            for (int j = 0; j < 4; ++j) acc[i][j] = 0.f;

#pragma unroll
        for (int kc = 0; kc < 2; ++kc) {
            const int k0 = kt * 128 + kc * 64;
            if (kc) __syncthreads();

            // A tile: 32 m x 64 k, folded over the 4 j-split partials
#pragma unroll
            for (int r = 0; r < 2; ++r) {
                const int lin = t + r * 256;        // 512 float4 slots
                const int row = lin >> 4;           // m row 0..31
                const int kq  = (lin & 15) * 4;
                const int aoff = (m0 + row) * NE + k0 + kq;
                float4 a = *(const float4*)&g_embp[0][aoff];
#pragma unroll
                for (int p = 1; p < JSPLIT; ++p) {
                    const float4 v = *(const float4*)&g_embp[p][aoff];
                    a.x += v.x; a.y += v.y; a.z += v.z; a.w += v.w;
                }
                sm.g.a[kq + 0][row] = a.x;
                sm.g.a[kq + 1][row] = a.y;
                sm.g.a[kq + 2][row] = a.z;
                sm.g.a[kq + 3][row] = a.w;
            }
            // B tile: 64 n x 64 k
#pragma unroll
            for (int r = 0; r < 4; ++r) {
                const int lin = t + r * 256;        // 1024 float4 slots
                const int row = lin >> 4;           // n row 0..63
                const int kq  = (lin & 15) * 4;
                const float4 b4 = *(const float4*)&w[(n0 + row) * NE + k0 + kq];
                sm.g.b[kq + 0][row] = b4.x;
                sm.g.b[kq + 1][row] = b4.y;
                sm.g.b[kq + 2][row] = b4.z;
                sm.g.b[kq + 3][row] = b4.w;
            }
            __syncthreads();

#pragma unroll 8
            for (int kk = 0; kk < 64; ++kk) {
                const float2 av = *(const float2*)&sm.g.a[kk][ty * 2];
                const float4 bv = *(const float4*)&sm.g.b[kk][tx * 4];
                const float a2[2] = {av.x, av.y};
                const float b4[4] = {bv.x, bv.y, bv.z, bv.w};
#pragma unroll
                for (int i = 0; i < 2; ++i)
#pragma unroll
                    for (int j = 0; j < 4; ++j)
                        acc[i][j] = fmaf(a2[i], b4[j], acc[i][j]);
            }
        }

        // Split-K accumulate into the bias-initialized output.
#pragma unroll
        for (int i = 0; i < 2; ++i) {
            float* op = &out[(m0 + ty * 2 + i) * NE + n0 + tx * 4];
#pragma unroll
            for (int j = 0; j < 4; ++j)
                atomicAdd(op + j, acc[i][j]);
        }
    }
}

extern "C" void kernel_launch(void* const* d_in, const int* in_sizes, int n_in,
                              void* d_out, int out_size) {
    const float* x    = (const float*)d_in[0];  // [16,1,512,512]
    // d_in[1] = W_q, d_in[2] = W_k: mathematically dead (softmax cols sum to 1)
    const float* wv   = (const float*)d_in[3];  // [1,16,512,512]
    const float* mlpw = (const float*)d_in[4];  // [512,512]
    const float* mlpb = (const float*)d_in[5];  // [512]
    float* out = (float*)d_out;                 // [16,16,512]

    fused_kernel<<<GRID, 256>>>(x, wv, mlpw, mlpb, out);
}